// round 4
// baseline (speedup 1.0000x reference)
#include <cuda_runtime.h>
#include <cuda_fp16.h>
#include <cstdint>

// Problem constants (fixed shapes from reference)
#define M_DIM 8192      // 4*2048
#define N_DIM 11008
#define K_DIM 4096
#define NGROUPS 32      // 4096/128
#define BM 128
#define BN 128
#define BK 64
#define THREADS 256

// Padded smem row stride: 64 halves + 8 pad = 72 halves = 144 bytes.
#define ROW_BYTES 144
#define TILE_BYTES (128 * ROW_BYTES)          // 18432 per operand
#define STAGE_BYTES (2 * TILE_BYTES)          // A + B = 36864
#define SMEM_TOTAL (2 * STAGE_BYTES)          // double buffered = 73728

// Scratch: dequantized fp16 operands (static device globals; no runtime alloc)
__device__ __half g_A[(size_t)M_DIM * K_DIM];   // x as fp16, row-major [M,K]
__device__ __half g_B[(size_t)N_DIM * K_DIM];   // W as fp16, row-major [N,K]

// Weight storage-mode flag: 1 = one int8 value widened per int32 element,
// 0 = packed int8 bytes. Written by detect_kernel, read by dequant kernel.
__device__ int g_w_wide;

static __device__ __forceinline__ uint32_t pack2(__half a, __half b) {
    __half2 h = __halves2half2(a, b);
    return *reinterpret_cast<uint32_t*>(&h);
}

// ---------------------------------------------------------------------------
// Kernel 0: detect weight storage format.
// If the buffer holds int32-widened int8 values, every word is in [-128,127].
// If it holds packed int8 bytes, a random word is outside that range with
// probability ~1 - 2^-24. Checking 4096 words makes misdetection impossible
// in practice. Deterministic (input-dependent only).
// ---------------------------------------------------------------------------
__global__ void detect_kernel(const int* __restrict__ w) {
    __shared__ int any_big;
    if (threadIdx.x == 0) any_big = 0;
    __syncthreads();
    int big = 0;
    for (int i = threadIdx.x; i < 4096; i += blockDim.x) {
        int v = w[i];
        if (v > 127 || v < -128) big = 1;
    }
    if (big) any_big = 1;   // benign race: all writers store 1
    __syncthreads();
    if (threadIdx.x == 0) g_w_wide = any_big ? 0 : 1;
}

// ---------------------------------------------------------------------------
// Kernel 1: fp32 -> fp16 convert of x (8 elems/thread, 16B stores)
// ---------------------------------------------------------------------------
__global__ void convert_x_kernel(const float* __restrict__ x) {
    size_t i = (size_t)blockIdx.x * blockDim.x + threadIdx.x;
    if (i >= (size_t)M_DIM * K_DIM / 8) return;
    const float4* p = reinterpret_cast<const float4*>(x) + i * 2;
    float4 u = p[0];
    float4 v = p[1];
    uint4 o;
    o.x = pack2(__float2half_rn(u.x), __float2half_rn(u.y));
    o.y = pack2(__float2half_rn(u.z), __float2half_rn(u.w));
    o.z = pack2(__float2half_rn(v.x), __float2half_rn(v.y));
    o.w = pack2(__float2half_rn(v.z), __float2half_rn(v.w));
    reinterpret_cast<uint4*>(g_A)[i] = o;
}

// ---------------------------------------------------------------------------
// Kernel 2: weight dequant, 8 values/thread. Handles both storage modes.
// ---------------------------------------------------------------------------
__global__ void dequant_w_kernel(const void* __restrict__ wq,
                                 const float* __restrict__ scales) {
    size_t i = (size_t)blockIdx.x * blockDim.x + threadIdx.x;
    if (i >= (size_t)N_DIM * K_DIM / 8) return;
    size_t kc = i % (K_DIM / 8);   // 8-value chunk along K (0..511)
    size_t n  = i / (K_DIM / 8);
    float s = scales[n * NGROUPS + (kc >> 4)];  // kc*8/128 == kc/16

    int q[8];
    if (g_w_wide) {
        // One int8 value per int32 element.
        const int4* p = reinterpret_cast<const int4*>(wq) + i * 2;
        int4 a = p[0];
        int4 b = p[1];
        q[0] = a.x; q[1] = a.y; q[2] = a.z; q[3] = a.w;
        q[4] = b.x; q[5] = b.y; q[6] = b.z; q[7] = b.w;
    } else {
        // Packed int8 bytes.
        int2 w = reinterpret_cast<const int2*>(wq)[i];
        int lo = w.x, hi = w.y;
#pragma unroll
        for (int b = 0; b < 4; b++) {
            q[b]     = (int)(int8_t)(lo >> (8 * b));
            q[b + 4] = (int)(int8_t)(hi >> (8 * b));
        }
    }

    __half h[8];
#pragma unroll
    for (int j = 0; j < 8; j++) h[j] = __float2half_rn((float)q[j] * s);

    uint4 o;
    o.x = pack2(h[0], h[1]);
    o.y = pack2(h[2], h[3]);
    o.z = pack2(h[4], h[5]);
    o.w = pack2(h[6], h[7]);
    reinterpret_cast<uint4*>(g_B)[i] = o;
}

// ---------------------------------------------------------------------------
// GEMM: C[M,N] = A[M,K] * B[N,K]^T (fp16 in, fp32 acc), epilogue fp16 +bias
// 128x128x64 tile, 256 threads (8 warps, 2x4), warp tile 64x32.
// mma.sync.m16n8k16 with DIRECT per-fragment LDS loads from padded smem.
// (unchanged from round 3 — held constant while the input fix is validated)
// ---------------------------------------------------------------------------
__device__ __forceinline__ void cp_async16(uint32_t dst, const void* src) {
    asm volatile("cp.async.cg.shared.global [%0], [%1], 16;\n" ::"r"(dst), "l"(src));
}
__device__ __forceinline__ void cp_commit() {
    asm volatile("cp.async.commit_group;\n");
}
__device__ __forceinline__ void cp_wait0() {
    asm volatile("cp.async.wait_group 0;\n");
}
__device__ __forceinline__ void mma_16816(float* c, const uint32_t* a,
                                          uint32_t b0, uint32_t b1) {
    asm volatile(
        "mma.sync.aligned.m16n8k16.row.col.f32.f16.f16.f32 "
        "{%0,%1,%2,%3},{%4,%5,%6,%7},{%8,%9},{%0,%1,%2,%3};\n"
        : "+f"(c[0]), "+f"(c[1]), "+f"(c[2]), "+f"(c[3])
        : "r"(a[0]), "r"(a[1]), "r"(a[2]), "r"(a[3]), "r"(b0), "r"(b1));
}

__global__ void __launch_bounds__(THREADS, 1)
gemm_kernel(const float* __restrict__ bias, float* __restrict__ out) {
    extern __shared__ char smem[];
    const int tid  = threadIdx.x;
    const int lane = tid & 31;
    const int warp = tid >> 5;
    const int wm = warp >> 2;       // 0..1  (M half)
    const int wn = warp & 3;        // 0..3  (N quarter)
    const int g    = lane >> 2;     // fragment group id 0..7
    const int tid4 = lane & 3;      // fragment thread-in-group 0..3
    const int bM = blockIdx.y * BM;
    const int bN = blockIdx.x * BN;

    const uint32_t smem_base = (uint32_t)__cvta_generic_to_shared(smem);

    float acc[4][4][4];
#pragma unroll
    for (int i = 0; i < 4; i++)
#pragma unroll
        for (int j = 0; j < 4; j++)
#pragma unroll
            for (int k = 0; k < 4; k++) acc[i][j][k] = 0.f;

    const int T = K_DIM / BK;  // 64

    auto issue = [&](int stage, int tile) {
        uint32_t baseA = smem_base + stage * STAGE_BYTES;
        uint32_t baseB = baseA + TILE_BYTES;
#pragma unroll
        for (int i = 0; i < 4; i++) {
            int idx = tid + i * THREADS;   // 0..1023
            int r = idx >> 3;              // 0..127
            int c = idx & 7;               // 0..7
            uint32_t off = (uint32_t)(r * ROW_BYTES + c * 16);
            const __half* srcA = g_A + (size_t)(bM + r) * K_DIM + tile * BK + c * 8;
            cp_async16(baseA + off, srcA);
            const __half* srcB = g_B + (size_t)(bN + r) * K_DIM + tile * BK + c * 8;
            cp_async16(baseB + off, srcB);
        }
    };

    issue(0, 0);
    cp_commit();

    for (int t = 0; t < T; t++) {
        cp_wait0();
        __syncthreads();
        if (t + 1 < T) {
            issue((t + 1) & 1, t + 1);
            cp_commit();
        }
        const char* stA = smem + (t & 1) * STAGE_BYTES;
        const char* stB = stA + TILE_BYTES;
#pragma unroll
        for (int ks = 0; ks < 4; ks++) {
            const int kb = ks * 16;  // k base (halves) within tile
            uint32_t a[4][4];
#pragma unroll
            for (int mt = 0; mt < 4; mt++) {
                const char* rp0 = stA + (wm * 64 + mt * 16 + g) * ROW_BYTES;
                const char* rp1 = rp0 + 8 * ROW_BYTES;
                int kof = (kb + 2 * tid4) * 2;  // byte offset along k
                a[mt][0] = *(const uint32_t*)(rp0 + kof);
                a[mt][1] = *(const uint32_t*)(rp1 + kof);
                a[mt][2] = *(const uint32_t*)(rp0 + kof + 16);
                a[mt][3] = *(const uint32_t*)(rp1 + kof + 16);
            }
            uint32_t b[4][2];
#pragma unroll
            for (int nt = 0; nt < 4; nt++) {
                const char* rp = stB + (wn * 32 + nt * 8 + g) * ROW_BYTES;
                int kof = (kb + 2 * tid4) * 2;
                b[nt][0] = *(const uint32_t*)(rp + kof);
                b[nt][1] = *(const uint32_t*)(rp + kof + 16);
            }
#pragma unroll
            for (int mt = 0; mt < 4; mt++) {
#pragma unroll
                for (int nt = 0; nt < 4; nt++) {
                    mma_16816(acc[mt][nt], a[mt], b[nt][0], b[nt][1]);
                }
            }
        }
        __syncthreads();
    }

    // Epilogue: match reference fp16 semantics: fp16(acc) + fp16(bias) -> fp32
#pragma unroll
    for (int mt = 0; mt < 4; mt++) {
#pragma unroll
        for (int nt = 0; nt < 4; nt++) {
            int row = bM + wm * 64 + mt * 16 + g;
            int col = bN + wn * 32 + nt * 8 + tid4 * 2;
            __half hb0 = __float2half_rn(bias[col]);
            __half hb1 = __float2half_rn(bias[col + 1]);
            float* c = acc[mt][nt];
            float2 v0;
            v0.x = __half2float(__hadd(__float2half_rn(c[0]), hb0));
            v0.y = __half2float(__hadd(__float2half_rn(c[1]), hb1));
            *reinterpret_cast<float2*>(out + (size_t)row * N_DIM + col) = v0;
            float2 v1;
            v1.x = __half2float(__hadd(__float2half_rn(c[2]), hb0));
            v1.y = __half2float(__hadd(__float2half_rn(c[3]), hb1));
            *reinterpret_cast<float2*>(out + (size_t)(row + 8) * N_DIM + col) = v1;
        }
    }
}

// ---------------------------------------------------------------------------
extern "C" void kernel_launch(void* const* d_in, const int* in_sizes, int n_in,
                              void* d_out, int out_size) {
    // Bind inputs by element count (all four are distinct).
    const float* x      = nullptr;   // 8192*4096  = 33554432
    const void*  wq     = nullptr;   // 11008*4096 = 45088768 (int8 OR int32-widened)
    const float* scales = nullptr;   // 11008*32   = 352256
    const float* bias   = nullptr;   // 11008
    for (int i = 0; i < n_in; i++) {
        switch (in_sizes[i]) {
            case 33554432: x      = (const float*)d_in[i]; break;
            case 45088768: wq     = d_in[i];               break;
            case 352256:   scales = (const float*)d_in[i]; break;
            case 11008:    bias   = (const float*)d_in[i]; break;
            default: break;
        }
    }
    float* out = (float*)d_out;

    cudaFuncSetAttribute(gemm_kernel, cudaFuncAttributeMaxDynamicSharedMemorySize,
                         SMEM_TOTAL);

    detect_kernel<<<1, 256>>>((const int*)wq);
    {
        size_t nthr = (size_t)M_DIM * K_DIM / 8;
        convert_x_kernel<<<(unsigned)((nthr + 255) / 256), 256>>>(x);
    }
    {
        size_t nthr = (size_t)N_DIM * K_DIM / 8;
        dequant_w_kernel<<<(unsigned)((nthr + 255) / 256), 256>>>(wq, scales);
    }
    {
        dim3 grid(N_DIM / BN, M_DIM / BM);  // (86, 64)
        gemm_kernel<<<grid, THREADS, SMEM_TOTAL>>>(bias, out);
    }
}

// round 6
// speedup vs baseline: 1.1203x; 1.1203x over previous
#include <cuda_runtime.h>
#include <cuda_fp16.h>
#include <cstdint>

// ---------------------------------------------------------------------------
// Problem constants
// ---------------------------------------------------------------------------
#define M_DIM 8192      // 4*2048
#define N_DIM 11008
#define K_DIM 4096
#define NGROUPS 32
#define BM 128
#define BN 128
#define BK 64
#define THREADS 512     // 16 warps, 4x4 warp grid, warp tile 32x32
#define T_ITERS (K_DIM / BK)   // 64
#define NSTAGES 3

// Stage: A tile 16KB + B tile 16KB (128 rows x 128B, XOR-swizzled)
#define OFF_B       16384
#define STAGE_BYTES 32768
#define SMEM_TOTAL  (NSTAGES * STAGE_BYTES)   // 96KB

// Scratch: dequantized fp16 operands (static device globals; no runtime alloc)
__device__ __half g_A[(size_t)M_DIM * K_DIM];   // x as fp16, row-major [M,K]
__device__ __half g_B[(size_t)N_DIM * K_DIM];   // W as fp16, row-major [N,K]
__device__ int g_w_wide;

static __device__ __forceinline__ uint32_t pack2(__half a, __half b) {
    __half2 h = __halves2half2(a, b);
    return *reinterpret_cast<uint32_t*>(&h);
}

// ---------------------------------------------------------------------------
// Pre-pass kernels (unchanged from passing round 4)
// ---------------------------------------------------------------------------
__global__ void detect_kernel(const int* __restrict__ w) {
    __shared__ int any_big;
    if (threadIdx.x == 0) any_big = 0;
    __syncthreads();
    int big = 0;
    for (int i = threadIdx.x; i < 4096; i += blockDim.x) {
        int v = w[i];
        if (v > 127 || v < -128) big = 1;
    }
    if (big) any_big = 1;
    __syncthreads();
    if (threadIdx.x == 0) g_w_wide = any_big ? 0 : 1;
}

__global__ void convert_x_kernel(const float* __restrict__ x) {
    size_t i = (size_t)blockIdx.x * blockDim.x + threadIdx.x;
    if (i >= (size_t)M_DIM * K_DIM / 8) return;
    const float4* p = reinterpret_cast<const float4*>(x) + i * 2;
    float4 u = p[0];
    float4 v = p[1];
    uint4 o;
    o.x = pack2(__float2half_rn(u.x), __float2half_rn(u.y));
    o.y = pack2(__float2half_rn(u.z), __float2half_rn(u.w));
    o.z = pack2(__float2half_rn(v.x), __float2half_rn(v.y));
    o.w = pack2(__float2half_rn(v.z), __float2half_rn(v.w));
    reinterpret_cast<uint4*>(g_A)[i] = o;
}

__global__ void dequant_w_kernel(const void* __restrict__ wq,
                                 const float* __restrict__ scales) {
    size_t i = (size_t)blockIdx.x * blockDim.x + threadIdx.x;
    if (i >= (size_t)N_DIM * K_DIM / 8) return;
    size_t kc = i % (K_DIM / 8);
    size_t n  = i / (K_DIM / 8);
    float s = scales[n * NGROUPS + (kc >> 4)];
    int q[8];
    if (g_w_wide) {
        const int4* p = reinterpret_cast<const int4*>(wq) + i * 2;
        int4 a = p[0];
        int4 b = p[1];
        q[0] = a.x; q[1] = a.y; q[2] = a.z; q[3] = a.w;
        q[4] = b.x; q[5] = b.y; q[6] = b.z; q[7] = b.w;
    } else {
        int2 w = reinterpret_cast<const int2*>(wq)[i];
#pragma unroll
        for (int b = 0; b < 4; b++) {
            q[b]     = (int)(int8_t)(w.x >> (8 * b));
            q[b + 4] = (int)(int8_t)(w.y >> (8 * b));
        }
    }
    __half h[8];
#pragma unroll
    for (int j = 0; j < 8; j++) h[j] = __float2half_rn((float)q[j] * s);
    uint4 o;
    o.x = pack2(h[0], h[1]);
    o.y = pack2(h[2], h[3]);
    o.z = pack2(h[4], h[5]);
    o.w = pack2(h[6], h[7]);
    reinterpret_cast<uint4*>(g_B)[i] = o;
}

// ---------------------------------------------------------------------------
// GEMM: C = A * B^T, fp16 mma.sync, fp32 acc; epilogue fp16(acc)+fp16(bias).
// 128x128x64 tile, 512 threads (16 warps, 4x4), warp tile 32x32,
// 3-stage cp.async pipeline, ldmatrix + XOR-swizzled smem,
// ONE __syncthreads per K-tile.
// ---------------------------------------------------------------------------
__device__ __forceinline__ void cp_async16(uint32_t dst, const void* src) {
    asm volatile("cp.async.cg.shared.global [%0], [%1], 16;\n" ::"r"(dst), "l"(src));
}
#define CP_COMMIT() asm volatile("cp.async.commit_group;\n")
#define CP_WAIT1()  asm volatile("cp.async.wait_group 1;\n")

__device__ __forceinline__ void ldsm_x4(uint32_t& r0, uint32_t& r1, uint32_t& r2,
                                        uint32_t& r3, uint32_t addr) {
    asm volatile("ldmatrix.sync.aligned.m8n8.x4.shared.b16 {%0,%1,%2,%3}, [%4];\n"
                 : "=r"(r0), "=r"(r1), "=r"(r2), "=r"(r3)
                 : "r"(addr));
}
__device__ __forceinline__ void mma_16816(float* c, const uint32_t* a,
                                          uint32_t b0, uint32_t b1) {
    asm volatile(
        "mma.sync.aligned.m16n8k16.row.col.f32.f16.f16.f32 "
        "{%0,%1,%2,%3},{%4,%5,%6,%7},{%8,%9},{%0,%1,%2,%3};\n"
        : "+f"(c[0]), "+f"(c[1]), "+f"(c[2]), "+f"(c[3])
        : "r"(a[0]), "r"(a[1]), "r"(a[2]), "r"(a[3]), "r"(b0), "r"(b1));
}

// Swizzled smem byte offset: row r (128B rows), 16B-chunk c
__device__ __forceinline__ uint32_t sw_off(int r, int c) {
    return (uint32_t)(r * 128 + ((c ^ (r & 7)) << 4));
}

__global__ void __launch_bounds__(THREADS, 1)
gemm_kernel(const float* __restrict__ bias, float* __restrict__ out) {
    extern __shared__ char smem[];
    const int tid  = threadIdx.x;
    const int lane = tid & 31;
    const int warp = tid >> 5;
    const int wm = warp >> 2;       // 0..3 (M quarter, 32 rows)
    const int wn = warp & 3;        // 0..3 (N quarter, 32 cols)
    const int bM = blockIdx.y * BM;
    const int bN = blockIdx.x * BN;

    const uint32_t smem_base = (uint32_t)__cvta_generic_to_shared(smem);

    float acc[2][4][4];
#pragma unroll
    for (int i = 0; i < 2; i++)
#pragma unroll
        for (int j = 0; j < 4; j++)
#pragma unroll
            for (int k = 0; k < 4; k++) acc[i][j][k] = 0.f;

    // cp.async fill of K-chunk t into stage s: per operand 128 rows x 8 chunks
    // of 16B = 1024 chunks; 512 threads -> 2 chunks each.
    auto issue = [&](int t, int s) {
        uint32_t baseA = smem_base + s * STAGE_BYTES;
        uint32_t baseB = baseA + OFF_B;
#pragma unroll
        for (int i = 0; i < 2; i++) {
            int idx = tid + i * THREADS;   // 0..1023
            int r = idx >> 3;              // 0..127
            int c = idx & 7;               // 0..7
            uint32_t off = sw_off(r, c);
            cp_async16(baseA + off, g_A + (size_t)(bM + r) * K_DIM + t * BK + c * 8);
            cp_async16(baseB + off, g_B + (size_t)(bN + r) * K_DIM + t * BK + c * 8);
        }
    };

    // Prologue: 2 stages in flight
    issue(0, 0);
    CP_COMMIT();
    issue(1, 1);
    CP_COMMIT();

    const int lr = lane & 15;
    const int lc = lane >> 4;

    for (int t = 0; t < T_ITERS; t++) {
        CP_WAIT1();          // group for chunk t complete (<=1 group pending)
        __syncthreads();     // also protects stage reuse: all warps done with t-1
        if (t + 2 < T_ITERS) issue(t + 2, (t + 2) % NSTAGES);
        CP_COMMIT();         // keep group accounting constant (may be empty)

        uint32_t baseA = smem_base + (t % NSTAGES) * STAGE_BYTES;
        uint32_t baseB = baseA + OFF_B;
#pragma unroll
        for (int ks = 0; ks < 4; ks++) {
            int chunk = ks * 2 + lc;  // 16B chunk along K for this lane
            uint32_t a[2][4];
#pragma unroll
            for (int mt = 0; mt < 2; mt++) {
                int row = wm * 32 + mt * 16 + lr;
                ldsm_x4(a[mt][0], a[mt][1], a[mt][2], a[mt][3],
                        baseA + sw_off(row, chunk));
            }
            uint32_t b[2][4];
#pragma unroll
            for (int p = 0; p < 2; p++) {
                int row = wn * 32 + p * 16 + lr;
                ldsm_x4(b[p][0], b[p][1], b[p][2], b[p][3],
                        baseB + sw_off(row, chunk));
            }
#pragma unroll
            for (int mt = 0; mt < 2; mt++) {
#pragma unroll
                for (int nt = 0; nt < 4; nt++) {
                    mma_16816(acc[mt][nt], a[mt],
                              b[nt >> 1][nt & 1], b[nt >> 1][(nt & 1) + 2]);
                }
            }
        }
    }

    // Epilogue: fp16(acc) + fp16(bias) -> fp32 (reference semantics)
    const int g    = lane >> 2;
    const int tid4 = lane & 3;
#pragma unroll
    for (int mt = 0; mt < 2; mt++) {
#pragma unroll
        for (int nt = 0; nt < 4; nt++) {
            int row = bM + wm * 32 + mt * 16 + g;
            int col = bN + wn * 32 + nt * 8 + tid4 * 2;
            __half hb0 = __float2half_rn(bias[col]);
            __half hb1 = __float2half_rn(bias[col + 1]);
            float* c = acc[mt][nt];
            float2 v0;
            v0.x = __half2float(__hadd(__float2half_rn(c[0]), hb0));
            v0.y = __half2float(__hadd(__float2half_rn(c[1]), hb1));
            *reinterpret_cast<float2*>(out + (size_t)row * N_DIM + col) = v0;
            float2 v1;
            v1.x = __half2float(__hadd(__float2half_rn(c[2]), hb0));
            v1.y = __half2float(__hadd(__float2half_rn(c[3]), hb1));
            *reinterpret_cast<float2*>(out + (size_t)(row + 8) * N_DIM + col) = v1;
        }
    }
}

// ---------------------------------------------------------------------------
extern "C" void kernel_launch(void* const* d_in, const int* in_sizes, int n_in,
                              void* d_out, int out_size) {
    const float* x      = nullptr;   // 33554432 fp32
    const void*  wq     = nullptr;   // 45088768 (int8 OR int32-widened)
    const float* scales = nullptr;   // 352256 fp32
    const float* bias   = nullptr;   // 11008 fp32
    for (int i = 0; i < n_in; i++) {
        switch (in_sizes[i]) {
            case 33554432: x      = (const float*)d_in[i]; break;
            case 45088768: wq     = d_in[i];               break;
            case 352256:   scales = (const float*)d_in[i]; break;
            case 11008:    bias   = (const float*)d_in[i]; break;
            default: break;
        }
    }
    float* out = (float*)d_out;

    cudaFuncSetAttribute(gemm_kernel, cudaFuncAttributeMaxDynamicSharedMemorySize,
                         SMEM_TOTAL);

    detect_kernel<<<1, 256>>>((const int*)wq);
    {
        size_t nthr = (size_t)M_DIM * K_DIM / 8;
        convert_x_kernel<<<(unsigned)((nthr + 255) / 256), 256>>>(x);
    }
    {
        size_t nthr = (size_t)N_DIM * K_DIM / 8;
        dequant_w_kernel<<<(unsigned)((nthr + 255) / 256), 256>>>(wq, scales);
    }
    {
        dim3 grid(N_DIM / BN, M_DIM / BM);  // (86, 64)
        gemm_kernel<<<grid, THREADS, SMEM_TOTAL>>>(bias, out);
    }
}

// round 7
// speedup vs baseline: 1.2595x; 1.1242x over previous
#include <cuda_runtime.h>
#include <cuda_fp16.h>
#include <cstdint>

// ---------------------------------------------------------------------------
// Problem constants
// ---------------------------------------------------------------------------
#define M_DIM 8192      // 4*2048
#define N_DIM 11008
#define K_DIM 4096
#define NGROUPS 32
#define BM 256
#define BN 128
#define BK 64
#define THREADS 512     // 16 warps: 4 (M) x 4 (N), warp tile 64x32
#define T_ITERS (K_DIM / BK)   // 64
#define NSTAGES 3

// Stage: A tile 32KB (256 rows x 128B) + B tile 16KB (128 rows x 128B)
#define OFF_B       32768
#define STAGE_BYTES 49152
#define SMEM_TOTAL  (NSTAGES * STAGE_BYTES)   // 144KB

// Scratch: dequantized fp16 operands (static device globals; no runtime alloc)
__device__ __half g_A[(size_t)M_DIM * K_DIM];   // x as fp16, row-major [M,K]
__device__ __half g_B[(size_t)N_DIM * K_DIM];   // W as fp16, row-major [N,K]
__device__ int g_w_wide;

static __device__ __forceinline__ uint32_t pack2(__half a, __half b) {
    __half2 h = __halves2half2(a, b);
    return *reinterpret_cast<uint32_t*>(&h);
}

// ---------------------------------------------------------------------------
// Pre-pass kernels (unchanged)
// ---------------------------------------------------------------------------
__global__ void detect_kernel(const int* __restrict__ w) {
    __shared__ int any_big;
    if (threadIdx.x == 0) any_big = 0;
    __syncthreads();
    int big = 0;
    for (int i = threadIdx.x; i < 4096; i += blockDim.x) {
        int v = w[i];
        if (v > 127 || v < -128) big = 1;
    }
    if (big) any_big = 1;
    __syncthreads();
    if (threadIdx.x == 0) g_w_wide = any_big ? 0 : 1;
}

__global__ void convert_x_kernel(const float* __restrict__ x) {
    size_t i = (size_t)blockIdx.x * blockDim.x + threadIdx.x;
    if (i >= (size_t)M_DIM * K_DIM / 8) return;
    const float4* p = reinterpret_cast<const float4*>(x) + i * 2;
    float4 u = p[0];
    float4 v = p[1];
    uint4 o;
    o.x = pack2(__float2half_rn(u.x), __float2half_rn(u.y));
    o.y = pack2(__float2half_rn(u.z), __float2half_rn(u.w));
    o.z = pack2(__float2half_rn(v.x), __float2half_rn(v.y));
    o.w = pack2(__float2half_rn(v.z), __float2half_rn(v.w));
    reinterpret_cast<uint4*>(g_A)[i] = o;
}

__global__ void dequant_w_kernel(const void* __restrict__ wq,
                                 const float* __restrict__ scales) {
    size_t i = (size_t)blockIdx.x * blockDim.x + threadIdx.x;
    if (i >= (size_t)N_DIM * K_DIM / 8) return;
    size_t kc = i % (K_DIM / 8);
    size_t n  = i / (K_DIM / 8);
    float s = scales[n * NGROUPS + (kc >> 4)];
    int q[8];
    if (g_w_wide) {
        const int4* p = reinterpret_cast<const int4*>(wq) + i * 2;
        int4 a = p[0];
        int4 b = p[1];
        q[0] = a.x; q[1] = a.y; q[2] = a.z; q[3] = a.w;
        q[4] = b.x; q[5] = b.y; q[6] = b.z; q[7] = b.w;
    } else {
        int2 w = reinterpret_cast<const int2*>(wq)[i];
#pragma unroll
        for (int b = 0; b < 4; b++) {
            q[b]     = (int)(int8_t)(w.x >> (8 * b));
            q[b + 4] = (int)(int8_t)(w.y >> (8 * b));
        }
    }
    __half h[8];
#pragma unroll
    for (int j = 0; j < 8; j++) h[j] = __float2half_rn((float)q[j] * s);
    uint4 o;
    o.x = pack2(h[0], h[1]);
    o.y = pack2(h[2], h[3]);
    o.z = pack2(h[4], h[5]);
    o.w = pack2(h[6], h[7]);
    reinterpret_cast<uint4*>(g_B)[i] = o;
}

// ---------------------------------------------------------------------------
// GEMM: C = A * B^T, fp16 mma.sync, fp32 acc; epilogue fp16(acc)+fp16(bias).
// 256x128x64 tile, 512 threads (16 warps, 4x4), warp tile 64x32,
// 3-stage cp.async pipeline, ldmatrix + XOR-swizzled smem,
// one __syncthreads per K-tile.
// ---------------------------------------------------------------------------
__device__ __forceinline__ void cp_async16(uint32_t dst, const void* src) {
    asm volatile("cp.async.cg.shared.global [%0], [%1], 16;\n" ::"r"(dst), "l"(src));
}
#define CP_COMMIT() asm volatile("cp.async.commit_group;\n")
#define CP_WAIT1()  asm volatile("cp.async.wait_group 1;\n")

__device__ __forceinline__ void ldsm_x4(uint32_t& r0, uint32_t& r1, uint32_t& r2,
                                        uint32_t& r3, uint32_t addr) {
    asm volatile("ldmatrix.sync.aligned.m8n8.x4.shared.b16 {%0,%1,%2,%3}, [%4];\n"
                 : "=r"(r0), "=r"(r1), "=r"(r2), "=r"(r3)
                 : "r"(addr));
}
__device__ __forceinline__ void mma_16816(float* c, const uint32_t* a,
                                          uint32_t b0, uint32_t b1) {
    asm volatile(
        "mma.sync.aligned.m16n8k16.row.col.f32.f16.f16.f32 "
        "{%0,%1,%2,%3},{%4,%5,%6,%7},{%8,%9},{%0,%1,%2,%3};\n"
        : "+f"(c[0]), "+f"(c[1]), "+f"(c[2]), "+f"(c[3])
        : "r"(a[0]), "r"(a[1]), "r"(a[2]), "r"(a[3]), "r"(b0), "r"(b1));
}

// Swizzled smem byte offset: row r (128B rows), 16B-chunk c
__device__ __forceinline__ uint32_t sw_off(int r, int c) {
    return (uint32_t)(r * 128 + ((c ^ (r & 7)) << 4));
}

__global__ void __launch_bounds__(THREADS, 1)
gemm_kernel(const float* __restrict__ bias, float* __restrict__ out) {
    extern __shared__ char smem[];
    const int tid  = threadIdx.x;
    const int lane = tid & 31;
    const int warp = tid >> 5;
    const int wm = warp >> 2;       // 0..3 (M: 64 rows each)
    const int wn = warp & 3;        // 0..3 (N: 32 cols each)
    const int bM = blockIdx.y * BM;
    const int bN = blockIdx.x * BN;

    const uint32_t smem_base = (uint32_t)__cvta_generic_to_shared(smem);

    float acc[4][4][4];
#pragma unroll
    for (int i = 0; i < 4; i++)
#pragma unroll
        for (int j = 0; j < 4; j++)
#pragma unroll
            for (int k = 0; k < 4; k++) acc[i][j][k] = 0.f;

    // cp.async fill of K-chunk t into stage s.
    // A: 256 rows x 8 chunks = 2048; B: 128 rows x 8 = 1024. 6 per thread.
    auto issue = [&](int t, int s) {
        uint32_t baseA = smem_base + s * STAGE_BYTES;
        uint32_t baseB = baseA + OFF_B;
        const __half* gA = g_A + t * BK;
        const __half* gB = g_B + t * BK;
#pragma unroll
        for (int i = 0; i < 4; i++) {
            int idx = tid + i * THREADS;   // 0..2047
            int r = idx >> 3;              // 0..255
            int c = idx & 7;               // 0..7
            cp_async16(baseA + sw_off(r, c), gA + (size_t)(bM + r) * K_DIM + c * 8);
        }
#pragma unroll
        for (int i = 0; i < 2; i++) {
            int idx = tid + i * THREADS;   // 0..1023
            int r = idx >> 3;              // 0..127
            int c = idx & 7;
            cp_async16(baseB + sw_off(r, c), gB + (size_t)(bN + r) * K_DIM + c * 8);
        }
    };

    // Prologue: 2 stages in flight
    issue(0, 0);
    CP_COMMIT();
    issue(1, 1);
    CP_COMMIT();

    const int lr = lane & 15;
    const int lc = lane >> 4;

    for (int t = 0; t < T_ITERS; t++) {
        CP_WAIT1();          // group for chunk t complete
        __syncthreads();     // all warps done with stage being refilled
        if (t + 2 < T_ITERS) issue(t + 2, (t + 2) % NSTAGES);
        CP_COMMIT();         // keep group accounting constant (may be empty)

        uint32_t baseA = smem_base + (t % NSTAGES) * STAGE_BYTES;
        uint32_t baseB = baseA + OFF_B;
#pragma unroll
        for (int ks = 0; ks < 4; ks++) {
            int chunk = ks * 2 + lc;  // 16B chunk along K for this lane
            uint32_t a[4][4];
#pragma unroll
            for (int mt = 0; mt < 4; mt++) {
                int row = wm * 64 + mt * 16 + lr;
                ldsm_x4(a[mt][0], a[mt][1], a[mt][2], a[mt][3],
                        baseA + sw_off(row, chunk));
            }
            uint32_t b[2][4];
#pragma unroll
            for (int p = 0; p < 2; p++) {
                int row = wn * 32 + p * 16 + lr;
                ldsm_x4(b[p][0], b[p][1], b[p][2], b[p][3],
                        baseB + sw_off(row, chunk));
            }
#pragma unroll
            for (int mt = 0; mt < 4; mt++) {
#pragma unroll
                for (int nt = 0; nt < 4; nt++) {
                    mma_16816(acc[mt][nt], a[mt],
                              b[nt >> 1][nt & 1], b[nt >> 1][(nt & 1) + 2]);
                }
            }
        }
    }

    // Epilogue: fp16(acc) + fp16(bias) -> fp32 (reference semantics)
    const int g    = lane >> 2;
    const int tid4 = lane & 3;
#pragma unroll
    for (int mt = 0; mt < 4; mt++) {
#pragma unroll
        for (int nt = 0; nt < 4; nt++) {
            int row = bM + wm * 64 + mt * 16 + g;
            int col = bN + wn * 32 + nt * 8 + tid4 * 2;
            __half hb0 = __float2half_rn(bias[col]);
            __half hb1 = __float2half_rn(bias[col + 1]);
            float* c = acc[mt][nt];
            float2 v0;
            v0.x = __half2float(__hadd(__float2half_rn(c[0]), hb0));
            v0.y = __half2float(__hadd(__float2half_rn(c[1]), hb1));
            *reinterpret_cast<float2*>(out + (size_t)row * N_DIM + col) = v0;
            float2 v1;
            v1.x = __half2float(__hadd(__float2half_rn(c[2]), hb0));
            v1.y = __half2float(__hadd(__float2half_rn(c[3]), hb1));
            *reinterpret_cast<float2*>(out + (size_t)(row + 8) * N_DIM + col) = v1;
        }
    }
}

// ---------------------------------------------------------------------------
extern "C" void kernel_launch(void* const* d_in, const int* in_sizes, int n_in,
                              void* d_out, int out_size) {
    const float* x      = nullptr;   // 33554432 fp32
    const void*  wq     = nullptr;   // 45088768 (int8 OR int32-widened)
    const float* scales = nullptr;   // 352256 fp32
    const float* bias   = nullptr;   // 11008 fp32
    for (int i = 0; i < n_in; i++) {
        switch (in_sizes[i]) {
            case 33554432: x      = (const float*)d_in[i]; break;
            case 45088768: wq     = d_in[i];               break;
            case 352256:   scales = (const float*)d_in[i]; break;
            case 11008:    bias   = (const float*)d_in[i]; break;
            default: break;
        }
    }
    float* out = (float*)d_out;

    cudaFuncSetAttribute(gemm_kernel, cudaFuncAttributeMaxDynamicSharedMemorySize,
                         SMEM_TOTAL);

    detect_kernel<<<1, 256>>>((const int*)wq);
    {
        size_t nthr = (size_t)M_DIM * K_DIM / 8;
        convert_x_kernel<<<(unsigned)((nthr + 255) / 256), 256>>>(x);
    }
    {
        size_t nthr = (size_t)N_DIM * K_DIM / 8;
        dequant_w_kernel<<<(unsigned)((nthr + 255) / 256), 256>>>(wq, scales);
    }
    {
        dim3 grid(N_DIM / BN, M_DIM / BM);  // (86, 32)
        gemm_kernel<<<grid, THREADS, SMEM_TOTAL>>>(bias, out);
    }
}

// round 9
// speedup vs baseline: 1.3157x; 1.0447x over previous
#include <cuda_runtime.h>
#include <cuda_fp16.h>
#include <cstdint>

// ---------------------------------------------------------------------------
// Problem constants
// ---------------------------------------------------------------------------
#define M_DIM 8192      // 4*2048
#define N_DIM 11008
#define K_DIM 4096
#define NGROUPS 32
#define BM 128
#define BN 128
#define BK 64
#define THREADS 256     // 8 warps: 2 (M) x 4 (N), warp tile 64x32
#define T_ITERS (K_DIM / BK)   // 64
#define NSTAGES 3

// Stage: A tile 16KB + B tile 16KB (128 rows x 128B, XOR-swizzled)
#define OFF_B       16384
#define STAGE_BYTES 32768
#define SMEM_TOTAL  (NSTAGES * STAGE_BYTES)   // 96KB -> 2 CTAs/SM

// Scratch: dequantized fp16 operands (static device globals; no runtime alloc)
__device__ __half g_A[(size_t)M_DIM * K_DIM];   // x as fp16, row-major [M,K]
__device__ __half g_B[(size_t)N_DIM * K_DIM];   // W as fp16, row-major [N,K]
__device__ int g_w_wide;

static __device__ __forceinline__ uint32_t pack2(__half a, __half b) {
    __half2 h = __halves2half2(a, b);
    return *reinterpret_cast<uint32_t*>(&h);
}

// ---------------------------------------------------------------------------
// Pre-pass kernels (unchanged)
// ---------------------------------------------------------------------------
__global__ void detect_kernel(const int* __restrict__ w) {
    __shared__ int any_big;
    if (threadIdx.x == 0) any_big = 0;
    __syncthreads();
    int big = 0;
    for (int i = threadIdx.x; i < 4096; i += blockDim.x) {
        int v = w[i];
        if (v > 127 || v < -128) big = 1;
    }
    if (big) any_big = 1;
    __syncthreads();
    if (threadIdx.x == 0) g_w_wide = any_big ? 0 : 1;
}

__global__ void convert_x_kernel(const float* __restrict__ x) {
    size_t i = (size_t)blockIdx.x * blockDim.x + threadIdx.x;
    if (i >= (size_t)M_DIM * K_DIM / 8) return;
    const float4* p = reinterpret_cast<const float4*>(x) + i * 2;
    float4 u = p[0];
    float4 v = p[1];
    uint4 o;
    o.x = pack2(__float2half_rn(u.x), __float2half_rn(u.y));
    o.y = pack2(__float2half_rn(u.z), __float2half_rn(u.w));
    o.z = pack2(__float2half_rn(v.x), __float2half_rn(v.y));
    o.w = pack2(__float2half_rn(v.z), __float2half_rn(v.w));
    reinterpret_cast<uint4*>(g_A)[i] = o;
}

__global__ void dequant_w_kernel(const void* __restrict__ wq,
                                 const float* __restrict__ scales) {
    size_t i = (size_t)blockIdx.x * blockDim.x + threadIdx.x;
    if (i >= (size_t)N_DIM * K_DIM / 8) return;
    size_t kc = i % (K_DIM / 8);
    size_t n  = i / (K_DIM / 8);
    float s = scales[n * NGROUPS + (kc >> 4)];
    int q[8];
    if (g_w_wide) {
        const int4* p = reinterpret_cast<const int4*>(wq) + i * 2;
        int4 a = p[0];
        int4 b = p[1];
        q[0] = a.x; q[1] = a.y; q[2] = a.z; q[3] = a.w;
        q[4] = b.x; q[5] = b.y; q[6] = b.z; q[7] = b.w;
    } else {
        int2 w = reinterpret_cast<const int2*>(wq)[i];
#pragma unroll
        for (int b = 0; b < 4; b++) {
            q[b]     = (int)(int8_t)(w.x >> (8 * b));
            q[b + 4] = (int)(int8_t)(w.y >> (8 * b));
        }
    }
    __half h[8];
#pragma unroll
    for (int j = 0; j < 8; j++) h[j] = __float2half_rn((float)q[j] * s);
    uint4 o;
    o.x = pack2(h[0], h[1]);
    o.y = pack2(h[2], h[3]);
    o.z = pack2(h[4], h[5]);
    o.w = pack2(h[6], h[7]);
    reinterpret_cast<uint4*>(g_B)[i] = o;
}

// ---------------------------------------------------------------------------
// GEMM: C = A * B^T, fp16 mma.sync, fp32 acc; epilogue fp16(acc)+fp16(bias).
// 128x128x64 tile, 256 threads (8 warps, 2x4), warp tile 64x32,
// 3-stage cp.async pipeline, ldmatrix + XOR-swizzled smem,
// one __syncthreads per K-tile, TWO CTAs per SM (barrier decorrelation).
// ---------------------------------------------------------------------------
__device__ __forceinline__ void cp_async16(uint32_t dst, const void* src) {
    asm volatile("cp.async.cg.shared.global [%0], [%1], 16;\n" ::"r"(dst), "l"(src));
}
#define CP_COMMIT() asm volatile("cp.async.commit_group;\n")
#define CP_WAIT1()  asm volatile("cp.async.wait_group 1;\n")

__device__ __forceinline__ void ldsm_x4(uint32_t& r0, uint32_t& r1, uint32_t& r2,
                                        uint32_t& r3, uint32_t addr) {
    asm volatile("ldmatrix.sync.aligned.m8n8.x4.shared.b16 {%0,%1,%2,%3}, [%4];\n"
                 : "=r"(r0), "=r"(r1), "=r"(r2), "=r"(r3)
                 : "r"(addr));
}
__device__ __forceinline__ void mma_16816(float* c, const uint32_t* a,
                                          uint32_t b0, uint32_t b1) {
    asm volatile(
        "mma.sync.aligned.m16n8k16.row.col.f32.f16.f16.f32 "
        "{%0,%1,%2,%3},{%4,%5,%6,%7},{%8,%9},{%0,%1,%2,%3};\n"
        : "+f"(c[0]), "+f"(c[1]), "+f"(c[2]), "+f"(c[3])
        : "r"(a[0]), "r"(a[1]), "r"(a[2]), "r"(a[3]), "r"(b0), "r"(b1));
}

// Swizzled smem byte offset: row r (128B rows), 16B-chunk c
__device__ __forceinline__ uint32_t sw_off(int r, int c) {
    return (uint32_t)(r * 128 + ((c ^ (r & 7)) << 4));
}

__global__ void __launch_bounds__(THREADS, 2)
gemm_kernel(const float* __restrict__ bias, float* __restrict__ out) {
    extern __shared__ char smem[];
    const int tid  = threadIdx.x;
    const int lane = tid & 31;
    const int warp = tid >> 5;
    const int wm = warp >> 2;       // 0..1 (M: 64 rows each)
    const int wn = warp & 3;        // 0..3 (N: 32 cols each)
    const int bM = blockIdx.y * BM;
    const int bN = blockIdx.x * BN;

    const uint32_t smem_base = (uint32_t)__cvta_generic_to_shared(smem);

    float acc[4][4][4];
#pragma unroll
    for (int i = 0; i < 4; i++)
#pragma unroll
        for (int j = 0; j < 4; j++)
#pragma unroll
            for (int k = 0; k < 4; k++) acc[i][j][k] = 0.f;

    // cp.async fill of K-chunk t into stage s: per operand 1024 16B chunks;
    // 256 threads -> 4 chunks each per operand.
    auto issue = [&](int t, int s) {
        uint32_t baseA = smem_base + s * STAGE_BYTES;
        uint32_t baseB = baseA + OFF_B;
        const __half* gA = g_A + t * BK;
        const __half* gB = g_B + t * BK;
#pragma unroll
        for (int i = 0; i < 4; i++) {
            int idx = tid + i * THREADS;   // 0..1023
            int r = idx >> 3;              // 0..127
            int c = idx & 7;               // 0..7
            uint32_t off = sw_off(r, c);
            cp_async16(baseA + off, gA + (size_t)(bM + r) * K_DIM + c * 8);
            cp_async16(baseB + off, gB + (size_t)(bN + r) * K_DIM + c * 8);
        }
    };

    // Prologue: 2 stages in flight
    issue(0, 0);
    CP_COMMIT();
    issue(1, 1);
    CP_COMMIT();

    const int lr = lane & 15;
    const int lc = lane >> 4;

    for (int t = 0; t < T_ITERS; t++) {
        CP_WAIT1();          // group for chunk t complete
        __syncthreads();     // all warps done with stage being refilled
        if (t + 2 < T_ITERS) issue(t + 2, (t + 2) % NSTAGES);
        CP_COMMIT();         // keep group accounting constant (may be empty)

        uint32_t baseA = smem_base + (t % NSTAGES) * STAGE_BYTES;
        uint32_t baseB = baseA + OFF_B;
#pragma unroll
        for (int ks = 0; ks < 4; ks++) {
            int chunk = ks * 2 + lc;  // 16B chunk along K for this lane
            uint32_t a[4][4];
#pragma unroll
            for (int mt = 0; mt < 4; mt++) {
                int row = wm * 64 + mt * 16 + lr;
                ldsm_x4(a[mt][0], a[mt][1], a[mt][2], a[mt][3],
                        baseA + sw_off(row, chunk));
            }
            uint32_t b[2][4];
#pragma unroll
            for (int p = 0; p < 2; p++) {
                int row = wn * 32 + p * 16 + lr;
                ldsm_x4(b[p][0], b[p][1], b[p][2], b[p][3],
                        baseB + sw_off(row, chunk));
            }
#pragma unroll
            for (int mt = 0; mt < 4; mt++) {
#pragma unroll
                for (int nt = 0; nt < 4; nt++) {
                    mma_16816(acc[mt][nt], a[mt],
                              b[nt >> 1][nt & 1], b[nt >> 1][(nt & 1) + 2]);
                }
            }
        }
    }

    // Epilogue: fp16(acc) + fp16(bias) -> fp32 (reference semantics)
    const int g    = lane >> 2;
    const int tid4 = lane & 3;
#pragma unroll
    for (int mt = 0; mt < 4; mt++) {
#pragma unroll
        for (int nt = 0; nt < 4; nt++) {
            int row = bM + wm * 64 + mt * 16 + g;
            int col = bN + wn * 32 + nt * 8 + tid4 * 2;
            __half hb0 = __float2half_rn(bias[col]);
            __half hb1 = __float2half_rn(bias[col + 1]);
            float* c = acc[mt][nt];
            float2 v0;
            v0.x = __half2float(__hadd(__float2half_rn(c[0]), hb0));
            v0.y = __half2float(__hadd(__float2half_rn(c[1]), hb1));
            *reinterpret_cast<float2*>(out + (size_t)row * N_DIM + col) = v0;
            float2 v1;
            v1.x = __half2float(__hadd(__float2half_rn(c[2]), hb0));
            v1.y = __half2float(__hadd(__float2half_rn(c[3]), hb1));
            *reinterpret_cast<float2*>(out + (size_t)(row + 8) * N_DIM + col) = v1;
        }
    }
}

// ---------------------------------------------------------------------------
extern "C" void kernel_launch(void* const* d_in, const int* in_sizes, int n_in,
                              void* d_out, int out_size) {
    const float* x      = nullptr;   // 33554432 fp32
    const void*  wq     = nullptr;   // 45088768 (int8 OR int32-widened)
    const float* scales = nullptr;   // 352256 fp32
    const float* bias   = nullptr;   // 11008 fp32
    for (int i = 0; i < n_in; i++) {
        switch (in_sizes[i]) {
            case 33554432: x      = (const float*)d_in[i]; break;
            case 45088768: wq     = d_in[i];               break;
            case 352256:   scales = (const float*)d_in[i]; break;
            case 11008:    bias   = (const float*)d_in[i]; break;
            default: break;
        }
    }
    float* out = (float*)d_out;

    cudaFuncSetAttribute(gemm_kernel, cudaFuncAttributeMaxDynamicSharedMemorySize,
                         SMEM_TOTAL);

    detect_kernel<<<1, 256>>>((const int*)wq);
    {
        size_t nthr = (size_t)M_DIM * K_DIM / 8;
        convert_x_kernel<<<(unsigned)((nthr + 255) / 256), 256>>>(x);
    }
    {
        size_t nthr = (size_t)N_DIM * K_DIM / 8;
        dequant_w_kernel<<<(unsigned)((nthr + 255) / 256), 256>>>(wq, scales);
    }
    {
        dim3 grid(N_DIM / BN, M_DIM / BM);  // (86, 64)
        gemm_kernel<<<grid, THREADS, SMEM_TOTAL>>>(bias, out);
    }
}

// round 11
// speedup vs baseline: 1.3425x; 1.0203x over previous
#include <cuda_runtime.h>
#include <cuda_fp16.h>
#include <cstdint>

// ---------------------------------------------------------------------------
// Problem constants
// ---------------------------------------------------------------------------
#define M_DIM 8192      // 4*2048
#define N_DIM 11008
#define K_DIM 4096
#define NGROUPS 32
#define BM 128
#define BN 128
#define BK 64
#define THREADS 256     // 8 warps: 2 (M) x 4 (N), warp tile 64x32
#define T_ITERS (K_DIM / BK)   // 64
#define NSTAGES 3

// Stage: A tile 16KB + B tile 16KB (128 rows x 128B, XOR-swizzled)
#define OFF_B       16384
#define STAGE_BYTES 32768
#define SMEM_TOTAL  (NSTAGES * STAGE_BYTES)   // 96KB -> 2 CTAs/SM

// Scratch: dequantized fp16 operands (static device globals; no runtime alloc)
__device__ __half g_A[(size_t)M_DIM * K_DIM];   // x as fp16, row-major [M,K]
__device__ __half g_B[(size_t)N_DIM * K_DIM];   // W as fp16, row-major [N,K]
__device__ int g_w_wide;

static __device__ __forceinline__ uint32_t pack2(__half a, __half b) {
    __half2 h = __halves2half2(a, b);
    return *reinterpret_cast<uint32_t*>(&h);
}

// ---------------------------------------------------------------------------
// Pre-pass kernels (unchanged)
// ---------------------------------------------------------------------------
__global__ void detect_kernel(const int* __restrict__ w) {
    __shared__ int any_big;
    if (threadIdx.x == 0) any_big = 0;
    __syncthreads();
    int big = 0;
    for (int i = threadIdx.x; i < 4096; i += blockDim.x) {
        int v = w[i];
        if (v > 127 || v < -128) big = 1;
    }
    if (big) any_big = 1;
    __syncthreads();
    if (threadIdx.x == 0) g_w_wide = any_big ? 0 : 1;
}

__global__ void convert_x_kernel(const float* __restrict__ x) {
    size_t i = (size_t)blockIdx.x * blockDim.x + threadIdx.x;
    if (i >= (size_t)M_DIM * K_DIM / 8) return;
    const float4* p = reinterpret_cast<const float4*>(x) + i * 2;
    float4 u = p[0];
    float4 v = p[1];
    uint4 o;
    o.x = pack2(__float2half_rn(u.x), __float2half_rn(u.y));
    o.y = pack2(__float2half_rn(u.z), __float2half_rn(u.w));
    o.z = pack2(__float2half_rn(v.x), __float2half_rn(v.y));
    o.w = pack2(__float2half_rn(v.z), __float2half_rn(v.w));
    reinterpret_cast<uint4*>(g_A)[i] = o;
}

__global__ void dequant_w_kernel(const void* __restrict__ wq,
                                 const float* __restrict__ scales) {
    size_t i = (size_t)blockIdx.x * blockDim.x + threadIdx.x;
    if (i >= (size_t)N_DIM * K_DIM / 8) return;
    size_t kc = i % (K_DIM / 8);
    size_t n  = i / (K_DIM / 8);
    float s = scales[n * NGROUPS + (kc >> 4)];
    int q[8];
    if (g_w_wide) {
        const int4* p = reinterpret_cast<const int4*>(wq) + i * 2;
        int4 a = p[0];
        int4 b = p[1];
        q[0] = a.x; q[1] = a.y; q[2] = a.z; q[3] = a.w;
        q[4] = b.x; q[5] = b.y; q[6] = b.z; q[7] = b.w;
    } else {
        int2 w = reinterpret_cast<const int2*>(wq)[i];
#pragma unroll
        for (int b = 0; b < 4; b++) {
            q[b]     = (int)(int8_t)(w.x >> (8 * b));
            q[b + 4] = (int)(int8_t)(w.y >> (8 * b));
        }
    }
    __half h[8];
#pragma unroll
    for (int j = 0; j < 8; j++) h[j] = __float2half_rn((float)q[j] * s);
    uint4 o;
    o.x = pack2(h[0], h[1]);
    o.y = pack2(h[2], h[3]);
    o.z = pack2(h[4], h[5]);
    o.w = pack2(h[6], h[7]);
    reinterpret_cast<uint4*>(g_B)[i] = o;
}

// ---------------------------------------------------------------------------
// GEMM: C = A * B^T, fp16 mma.sync, fp32 acc; epilogue fp16(acc)+fp16(bias).
// 128x128x64 tile, 256 threads (8 warps, 2x4), warp tile 64x32, 2 CTAs/SM.
// 3-stage cp.async pipeline; software-pipelined fragments:
//   - B fragments double-buffered across ks steps (loads overlap MMA issue)
//   - A fragments loaded per-mt immediately before use (short live ranges)
//   - precomputed row offsets / swizzle phases (less alu in the hot loop)
// ---------------------------------------------------------------------------
__device__ __forceinline__ void cp_async16(uint32_t dst, const void* src) {
    asm volatile("cp.async.cg.shared.global [%0], [%1], 16;\n" ::"r"(dst), "l"(src));
}
#define CP_COMMIT() asm volatile("cp.async.commit_group;\n")
#define CP_WAIT1()  asm volatile("cp.async.wait_group 1;\n")

__device__ __forceinline__ void ldsm_x4(uint32_t& r0, uint32_t& r1, uint32_t& r2,
                                        uint32_t& r3, uint32_t addr) {
    asm volatile("ldmatrix.sync.aligned.m8n8.x4.shared.b16 {%0,%1,%2,%3}, [%4];\n"
                 : "=r"(r0), "=r"(r1), "=r"(r2), "=r"(r3)
                 : "r"(addr));
}
__device__ __forceinline__ void mma_16816(float* c, const uint32_t* a,
                                          uint32_t b0, uint32_t b1) {
    asm volatile(
        "mma.sync.aligned.m16n8k16.row.col.f32.f16.f16.f32 "
        "{%0,%1,%2,%3},{%4,%5,%6,%7},{%8,%9},{%0,%1,%2,%3};\n"
        : "+f"(c[0]), "+f"(c[1]), "+f"(c[2]), "+f"(c[3])
        : "r"(a[0]), "r"(a[1]), "r"(a[2]), "r"(a[3]), "r"(b0), "r"(b1));
}

// Swizzled smem byte offset: row r (128B rows), 16B-chunk c
__device__ __forceinline__ uint32_t sw_off(int r, int c) {
    return (uint32_t)(r * 128 + ((c ^ (r & 7)) << 4));
}

__global__ void __launch_bounds__(THREADS, 2)
gemm_kernel(const float* __restrict__ bias, float* __restrict__ out) {
    extern __shared__ char smem[];
    const int tid  = threadIdx.x;
    const int lane = tid & 31;
    const int warp = tid >> 5;
    const int wm = warp >> 2;       // 0..1 (M: 64 rows each)
    const int wn = warp & 3;        // 0..3 (N: 32 cols each)
    const int bM = blockIdx.y * BM;
    const int bN = blockIdx.x * BN;

    const uint32_t smem_base = (uint32_t)__cvta_generic_to_shared(smem);

    float acc[4][4][4];
#pragma unroll
    for (int i = 0; i < 4; i++)
#pragma unroll
        for (int j = 0; j < 4; j++)
#pragma unroll
            for (int k = 0; k < 4; k++) acc[i][j][k] = 0.f;

    // Precompute fragment-row smem offsets and swizzle phases (loop-invariant)
    const int lr = lane & 15;
    const int lc = lane >> 4;
    uint32_t aoff[4], boff[2];
    int aph[4], bph[2];
#pragma unroll
    for (int mt = 0; mt < 4; mt++) {
        int r = wm * 64 + mt * 16 + lr;
        aoff[mt] = (uint32_t)(r * 128);
        aph[mt]  = r & 7;
    }
#pragma unroll
    for (int p = 0; p < 2; p++) {
        int r = wn * 32 + p * 16 + lr;
        boff[p] = (uint32_t)(OFF_B + r * 128);
        bph[p]  = r & 7;
    }

    // cp.async fill of K-chunk t into stage base wb.
    auto issue = [&](int t, uint32_t wb) {
        uint32_t baseB = wb + OFF_B;
        const __half* gA = g_A + t * BK;
        const __half* gB = g_B + t * BK;
#pragma unroll
        for (int i = 0; i < 4; i++) {
            int idx = tid + i * THREADS;   // 0..1023
            int r = idx >> 3;              // 0..127
            int c = idx & 7;               // 0..7
            uint32_t off = sw_off(r, c);
            cp_async16(wb + off, gA + (size_t)(bM + r) * K_DIM + c * 8);
            cp_async16(baseB + off, gB + (size_t)(bN + r) * K_DIM + c * 8);
        }
    };

    // Prologue: 2 stages in flight
    issue(0, smem_base);
    CP_COMMIT();
    issue(1, smem_base + STAGE_BYTES);
    CP_COMMIT();

    uint32_t rd = smem_base;                      // stage base for tile t
    uint32_t wr = smem_base + 2 * STAGE_BYTES;    // stage base for tile t+2
    const uint32_t stage_end = smem_base + 3 * STAGE_BYTES;

    for (int t = 0; t < T_ITERS; t++) {
        CP_WAIT1();          // cp group for tile t complete
        __syncthreads();     // cross-thread visibility + stage-reuse guard

        // Preload B fragments for ks=0 (buffer 0) before the cp.async burst:
        // ldsm latency hides the issue()'s alu/LSU work.
        uint32_t bfrag[2][8];
#pragma unroll
        for (int p = 0; p < 2; p++) {
            ldsm_x4(bfrag[0][p * 4 + 0], bfrag[0][p * 4 + 1],
                    bfrag[0][p * 4 + 2], bfrag[0][p * 4 + 3],
                    rd + boff[p] + (uint32_t)(((lc) ^ bph[p]) << 4));
        }

        if (t + 2 < T_ITERS) issue(t + 2, wr);
        CP_COMMIT();         // keep group accounting constant (may be empty)
        wr += STAGE_BYTES;
        if (wr == stage_end) wr = smem_base;

#pragma unroll
        for (int ks = 0; ks < 4; ks++) {
            const uint32_t* bc = bfrag[ks & 1];
            // Prefetch next ks's B fragments into the alternate buffer:
            // these 2 ldsm run underneath this ks's 16 MMAs.
            if (ks < 3) {
                uint32_t* bn = bfrag[(ks + 1) & 1];
                int chunk = (ks + 1) * 2 + lc;
#pragma unroll
                for (int p = 0; p < 2; p++) {
                    ldsm_x4(bn[p * 4 + 0], bn[p * 4 + 1], bn[p * 4 + 2], bn[p * 4 + 3],
                            rd + boff[p] + (uint32_t)((chunk ^ bph[p]) << 4));
                }
            }
            int chunk = ks * 2 + lc;
#pragma unroll
            for (int mt = 0; mt < 4; mt++) {
                uint32_t a[4];
                ldsm_x4(a[0], a[1], a[2], a[3],
                        rd + aoff[mt] + (uint32_t)((chunk ^ aph[mt]) << 4));
#pragma unroll
                for (int nt = 0; nt < 4; nt++) {
                    mma_16816(acc[mt][nt], a,
                              bc[(nt >> 1) * 4 + (nt & 1)],
                              bc[(nt >> 1) * 4 + (nt & 1) + 2]);
                }
            }
        }

        rd += STAGE_BYTES;
        if (rd == stage_end) rd = smem_base;
    }

    // Epilogue: fp16(acc) + fp16(bias) -> fp32 (reference semantics)
    const int g    = lane >> 2;
    const int tid4 = lane & 3;
#pragma unroll
    for (int mt = 0; mt < 4; mt++) {
#pragma unroll
        for (int nt = 0; nt < 4; nt++) {
            int row = bM + wm * 64 + mt * 16 + g;
            int col = bN + wn * 32 + nt * 8 + tid4 * 2;
            __half hb0 = __float2half_rn(bias[col]);
            __half hb1 = __float2half_rn(bias[col + 1]);
            float* c = acc[mt][nt];
            float2 v0;
            v0.x = __half2float(__hadd(__float2half_rn(c[0]), hb0));
            v0.y = __half2float(__hadd(__float2half_rn(c[1]), hb1));
            *reinterpret_cast<float2*>(out + (size_t)row * N_DIM + col) = v0;
            float2 v1;
            v1.x = __half2float(__hadd(__float2half_rn(c[2]), hb0));
            v1.y = __half2float(__hadd(__float2half_rn(c[3]), hb1));
            *reinterpret_cast<float2*>(out + (size_t)(row + 8) * N_DIM + col) = v1;
        }
    }
}

// ---------------------------------------------------------------------------
extern "C" void kernel_launch(void* const* d_in, const int* in_sizes, int n_in,
                              void* d_out, int out_size) {
    const float* x      = nullptr;   // 33554432 fp32
    const void*  wq     = nullptr;   // 45088768 (int8 OR int32-widened)
    const float* scales = nullptr;   // 352256 fp32
    const float* bias   = nullptr;   // 11008 fp32
    for (int i = 0; i < n_in; i++) {
        switch (in_sizes[i]) {
            case 33554432: x      = (const float*)d_in[i]; break;
            case 45088768: wq     = d_in[i];               break;
            case 352256:   scales = (const float*)d_in[i]; break;
            case 11008:    bias   = (const float*)d_in[i]; break;
            default: break;
        }
    }
    float* out = (float*)d_out;

    cudaFuncSetAttribute(gemm_kernel, cudaFuncAttributeMaxDynamicSharedMemorySize,
                         SMEM_TOTAL);

    detect_kernel<<<1, 256>>>((const int*)wq);
    {
        size_t nthr = (size_t)M_DIM * K_DIM / 8;
        convert_x_kernel<<<(unsigned)((nthr + 255) / 256), 256>>>(x);
    }
    {
        size_t nthr = (size_t)N_DIM * K_DIM / 8;
        dequant_w_kernel<<<(unsigned)((nthr + 255) / 256), 256>>>(wq, scales);
    }
    {
        dim3 grid(N_DIM / BN, M_DIM / BM);  // (86, 64)
        gemm_kernel<<<grid, THREADS, SMEM_TOTAL>>>(bias, out);
    }
}

// round 12
// speedup vs baseline: 1.3816x; 1.0291x over previous
#include <cuda_runtime.h>
#include <cuda_fp16.h>
#include <cstdint>

// ---------------------------------------------------------------------------
// Problem constants
// ---------------------------------------------------------------------------
#define M_DIM 8192      // 4*2048
#define N_DIM 11008
#define K_DIM 4096
#define NGROUPS 32
#define BM 128
#define BN 128
#define BK 64
#define THREADS 128     // 4 warps: 2 (M) x 2 (N), warp tile 64x64
#define T_ITERS (K_DIM / BK)   // 64
#define NSTAGES 3

// Stage: A tile 16KB + B tile 16KB (128 rows x 128B, XOR-swizzled)
#define OFF_B       16384
#define STAGE_BYTES 32768
#define SMEM_TOTAL  (NSTAGES * STAGE_BYTES)   // 96KB -> 2 CTAs/SM

// Scratch: dequantized fp16 operands (static device globals; no runtime alloc)
__device__ __half g_A[(size_t)M_DIM * K_DIM];   // x as fp16, row-major [M,K]
__device__ __half g_B[(size_t)N_DIM * K_DIM];   // W as fp16, row-major [N,K]
__device__ int g_w_wide;

static __device__ __forceinline__ uint32_t pack2(__half a, __half b) {
    __half2 h = __halves2half2(a, b);
    return *reinterpret_cast<uint32_t*>(&h);
}

// ---------------------------------------------------------------------------
// Pre-pass kernels (unchanged)
// ---------------------------------------------------------------------------
__global__ void detect_kernel(const int* __restrict__ w) {
    __shared__ int any_big;
    if (threadIdx.x == 0) any_big = 0;
    __syncthreads();
    int big = 0;
    for (int i = threadIdx.x; i < 4096; i += blockDim.x) {
        int v = w[i];
        if (v > 127 || v < -128) big = 1;
    }
    if (big) any_big = 1;
    __syncthreads();
    if (threadIdx.x == 0) g_w_wide = any_big ? 0 : 1;
}

__global__ void convert_x_kernel(const float* __restrict__ x) {
    size_t i = (size_t)blockIdx.x * blockDim.x + threadIdx.x;
    if (i >= (size_t)M_DIM * K_DIM / 8) return;
    const float4* p = reinterpret_cast<const float4*>(x) + i * 2;
    float4 u = p[0];
    float4 v = p[1];
    uint4 o;
    o.x = pack2(__float2half_rn(u.x), __float2half_rn(u.y));
    o.y = pack2(__float2half_rn(u.z), __float2half_rn(u.w));
    o.z = pack2(__float2half_rn(v.x), __float2half_rn(v.y));
    o.w = pack2(__float2half_rn(v.z), __float2half_rn(v.w));
    reinterpret_cast<uint4*>(g_A)[i] = o;
}

__global__ void dequant_w_kernel(const void* __restrict__ wq,
                                 const float* __restrict__ scales) {
    size_t i = (size_t)blockIdx.x * blockDim.x + threadIdx.x;
    if (i >= (size_t)N_DIM * K_DIM / 8) return;
    size_t kc = i % (K_DIM / 8);
    size_t n  = i / (K_DIM / 8);
    float s = scales[n * NGROUPS + (kc >> 4)];
    int q[8];
    if (g_w_wide) {
        const int4* p = reinterpret_cast<const int4*>(wq) + i * 2;
        int4 a = p[0];
        int4 b = p[1];
        q[0] = a.x; q[1] = a.y; q[2] = a.z; q[3] = a.w;
        q[4] = b.x; q[5] = b.y; q[6] = b.z; q[7] = b.w;
    } else {
        int2 w = reinterpret_cast<const int2*>(wq)[i];
#pragma unroll
        for (int b = 0; b < 4; b++) {
            q[b]     = (int)(int8_t)(w.x >> (8 * b));
            q[b + 4] = (int)(int8_t)(w.y >> (8 * b));
        }
    }
    __half h[8];
#pragma unroll
    for (int j = 0; j < 8; j++) h[j] = __float2half_rn((float)q[j] * s);
    uint4 o;
    o.x = pack2(h[0], h[1]);
    o.y = pack2(h[2], h[3]);
    o.z = pack2(h[4], h[5]);
    o.w = pack2(h[6], h[7]);
    reinterpret_cast<uint4*>(g_B)[i] = o;
}

// ---------------------------------------------------------------------------
// GEMM: C = A * B^T, fp16 mma.sync, fp32 acc; epilogue fp16(acc)+fp16(bias).
// 128x128x64 tile, 128 threads (4 warps, 2x2), warp tile 64x64, 2 CTAs/SM.
// Full 255-reg budget: mma:ldsm ratio 4:1, B frags double-buffered, A jit.
// ---------------------------------------------------------------------------
__device__ __forceinline__ void cp_async16(uint32_t dst, const void* src) {
    asm volatile("cp.async.cg.shared.global [%0], [%1], 16;\n" ::"r"(dst), "l"(src));
}
#define CP_COMMIT() asm volatile("cp.async.commit_group;\n")
#define CP_WAIT1()  asm volatile("cp.async.wait_group 1;\n")

__device__ __forceinline__ void ldsm_x4(uint32_t& r0, uint32_t& r1, uint32_t& r2,
                                        uint32_t& r3, uint32_t addr) {
    asm volatile("ldmatrix.sync.aligned.m8n8.x4.shared.b16 {%0,%1,%2,%3}, [%4];\n"
                 : "=r"(r0), "=r"(r1), "=r"(r2), "=r"(r3)
                 : "r"(addr));
}
__device__ __forceinline__ void mma_16816(float* c, const uint32_t* a,
                                          uint32_t b0, uint32_t b1) {
    asm volatile(
        "mma.sync.aligned.m16n8k16.row.col.f32.f16.f16.f32 "
        "{%0,%1,%2,%3},{%4,%5,%6,%7},{%8,%9},{%0,%1,%2,%3};\n"
        : "+f"(c[0]), "+f"(c[1]), "+f"(c[2]), "+f"(c[3])
        : "r"(a[0]), "r"(a[1]), "r"(a[2]), "r"(a[3]), "r"(b0), "r"(b1));
}

// Swizzled smem byte offset: row r (128B rows), 16B-chunk c
__device__ __forceinline__ uint32_t sw_off(int r, int c) {
    return (uint32_t)(r * 128 + ((c ^ (r & 7)) << 4));
}

__global__ void __launch_bounds__(THREADS, 2)
gemm_kernel(const float* __restrict__ bias, float* __restrict__ out) {
    extern __shared__ char smem[];
    const int tid  = threadIdx.x;
    const int lane = tid & 31;
    const int warp = tid >> 5;
    const int wm = warp >> 1;       // 0..1 (M: 64 rows each)
    const int wn = warp & 1;        // 0..1 (N: 64 cols each)
    const int bM = blockIdx.y * BM;
    const int bN = blockIdx.x * BN;

    const uint32_t smem_base = (uint32_t)__cvta_generic_to_shared(smem);

    float acc[4][8][4];
#pragma unroll
    for (int i = 0; i < 4; i++)
#pragma unroll
        for (int j = 0; j < 8; j++)
#pragma unroll
            for (int k = 0; k < 4; k++) acc[i][j][k] = 0.f;

    // Precompute fragment-row smem offsets and swizzle phases (loop-invariant)
    const int lr = lane & 15;
    const int lc = lane >> 4;
    uint32_t aoff[4], boff[4];
    int aph[4], bph[4];
#pragma unroll
    for (int mt = 0; mt < 4; mt++) {
        int r = wm * 64 + mt * 16 + lr;
        aoff[mt] = (uint32_t)(r * 128);
        aph[mt]  = r & 7;
    }
#pragma unroll
    for (int p = 0; p < 4; p++) {
        int r = wn * 64 + p * 16 + lr;
        boff[p] = (uint32_t)(OFF_B + r * 128);
        bph[p]  = r & 7;
    }

    // cp.async fill of K-chunk t into stage base wb.
    // Per operand 1024 16B chunks; 128 threads -> 8 chunks each per operand.
    auto issue = [&](int t, uint32_t wb) {
        uint32_t baseB = wb + OFF_B;
        const __half* gA = g_A + t * BK;
        const __half* gB = g_B + t * BK;
#pragma unroll
        for (int i = 0; i < 8; i++) {
            int idx = tid + i * THREADS;   // 0..1023
            int r = idx >> 3;              // 0..127
            int c = idx & 7;               // 0..7
            uint32_t off = sw_off(r, c);
            cp_async16(wb + off, gA + (size_t)(bM + r) * K_DIM + c * 8);
            cp_async16(baseB + off, gB + (size_t)(bN + r) * K_DIM + c * 8);
        }
    };

    // Prologue: 2 stages in flight
    issue(0, smem_base);
    CP_COMMIT();
    issue(1, smem_base + STAGE_BYTES);
    CP_COMMIT();

    uint32_t rd = smem_base;                      // stage base for tile t
    uint32_t wr = smem_base + 2 * STAGE_BYTES;    // stage base for tile t+2
    const uint32_t stage_end = smem_base + 3 * STAGE_BYTES;

    for (int t = 0; t < T_ITERS; t++) {
        CP_WAIT1();          // cp group for tile t complete
        __syncthreads();     // cross-thread visibility + stage-reuse guard

        // Preload B fragments for ks=0 (buffer 0): 4 ldsm covering n=64.
        uint32_t bfrag[2][16];
#pragma unroll
        for (int p = 0; p < 4; p++) {
            ldsm_x4(bfrag[0][p * 4 + 0], bfrag[0][p * 4 + 1],
                    bfrag[0][p * 4 + 2], bfrag[0][p * 4 + 3],
                    rd + boff[p] + (uint32_t)((lc ^ bph[p]) << 4));
        }

        if (t + 2 < T_ITERS) issue(t + 2, wr);
        CP_COMMIT();         // keep group accounting constant (may be empty)
        wr += STAGE_BYTES;
        if (wr == stage_end) wr = smem_base;

#pragma unroll
        for (int ks = 0; ks < 4; ks++) {
            const uint32_t* bc = bfrag[ks & 1];
            // Prefetch next ks's B fragments (4 ldsm) under this ks's 32 MMAs.
            if (ks < 3) {
                uint32_t* bn = bfrag[(ks + 1) & 1];
                int chunk = (ks + 1) * 2 + lc;
#pragma unroll
                for (int p = 0; p < 4; p++) {
                    ldsm_x4(bn[p * 4 + 0], bn[p * 4 + 1], bn[p * 4 + 2], bn[p * 4 + 3],
                            rd + boff[p] + (uint32_t)((chunk ^ bph[p]) << 4));
                }
            }
            int chunk = ks * 2 + lc;
#pragma unroll
            for (int mt = 0; mt < 4; mt++) {
                uint32_t a[4];
                ldsm_x4(a[0], a[1], a[2], a[3],
                        rd + aoff[mt] + (uint32_t)((chunk ^ aph[mt]) << 4));
#pragma unroll
                for (int nt = 0; nt < 8; nt++) {
                    mma_16816(acc[mt][nt], a,
                              bc[(nt >> 1) * 4 + (nt & 1)],
                              bc[(nt >> 1) * 4 + (nt & 1) + 2]);
                }
            }
        }

        rd += STAGE_BYTES;
        if (rd == stage_end) rd = smem_base;
    }

    // Epilogue: fp16(acc) + fp16(bias) -> fp32 (reference semantics)
    const int g    = lane >> 2;
    const int tid4 = lane & 3;
#pragma unroll
    for (int mt = 0; mt < 4; mt++) {
#pragma unroll
        for (int nt = 0; nt < 8; nt++) {
            int row = bM + wm * 64 + mt * 16 + g;
            int col = bN + wn * 64 + nt * 8 + tid4 * 2;
            __half hb0 = __float2half_rn(bias[col]);
            __half hb1 = __float2half_rn(bias[col + 1]);
            float* c = acc[mt][nt];
            float2 v0;
            v0.x = __half2float(__hadd(__float2half_rn(c[0]), hb0));
            v0.y = __half2float(__hadd(__float2half_rn(c[1]), hb1));
            *reinterpret_cast<float2*>(out + (size_t)row * N_DIM + col) = v0;
            float2 v1;
            v1.x = __half2float(__hadd(__float2half_rn(c[2]), hb0));
            v1.y = __half2float(__hadd(__float2half_rn(c[3]), hb1));
            *reinterpret_cast<float2*>(out + (size_t)(row + 8) * N_DIM + col) = v1;
        }
    }
}

// ---------------------------------------------------------------------------
extern "C" void kernel_launch(void* const* d_in, const int* in_sizes, int n_in,
                              void* d_out, int out_size) {
    const float* x      = nullptr;   // 33554432 fp32
    const void*  wq     = nullptr;   // 45088768 (int8 OR int32-widened)
    const float* scales = nullptr;   // 352256 fp32
    const float* bias   = nullptr;   // 11008 fp32
    for (int i = 0; i < n_in; i++) {
        switch (in_sizes[i]) {
            case 33554432: x      = (const float*)d_in[i]; break;
            case 45088768: wq     = d_in[i];               break;
            case 352256:   scales = (const float*)d_in[i]; break;
            case 11008:    bias   = (const float*)d_in[i]; break;
            default: break;
        }
    }
    float* out = (float*)d_out;

    cudaFuncSetAttribute(gemm_kernel, cudaFuncAttributeMaxDynamicSharedMemorySize,
                         SMEM_TOTAL);

    detect_kernel<<<1, 256>>>((const int*)wq);
    {
        size_t nthr = (size_t)M_DIM * K_DIM / 8;
        convert_x_kernel<<<(unsigned)((nthr + 255) / 256), 256>>>(x);
    }
    {
        size_t nthr = (size_t)N_DIM * K_DIM / 8;
        dequant_w_kernel<<<(unsigned)((nthr + 255) / 256), 256>>>(wq, scales);
    }
    {
        dim3 grid(N_DIM / BN, M_DIM / BM);  // (86, 64)
        gemm_kernel<<<grid, THREADS, SMEM_TOTAL>>>(bias, out);
    }
}